// round 3
// baseline (speedup 1.0000x reference)
#include <cuda_runtime.h>

#define BB 4
#define NB 8
#define HH 512
#define WW 512
#define HWs (HH*WW)           // 262144 = 2^18
#define KS 41
#define KR 20
#define SS 128
#define EPSF 1e-20f
#define BETAD 0.25

// ---------------- device scratch (referenced ONLY from device code) ----------------
__device__ float g_v[NB*KS];
__device__ float g_sp[BB*NB*HH*SS];
__device__ float g_ptmp[BB*HWs];
__device__ float g_panf[BB*HWs];
__device__ float g_dapf[BB*HWs];
__device__ float g_saapf[BB*HWs];
__device__ float g_dbpan[BB*HWs];
__device__ float g_sbbpan[BB*HWs];
__device__ float g_bufA[BB*NB*HWs];
__device__ float g_bufB[BB*NB*HWs];   // da_out (w=2)
__device__ float g_bufC[BB*NB*HWs];   // db_ms then thr
__device__ float g_bufD[BB*NB*HWs];
__device__ double g_acc[3];           // [0]=spec num, [1]=mask sum, [2]=struct sum

// ---------------- reduction helpers ----------------
__device__ __forceinline__ void block_reduce2(float a, float b, double* d0, double* d1) {
    #pragma unroll
    for (int o = 16; o; o >>= 1) {
        a += __shfl_down_sync(0xffffffffu, a, o);
        b += __shfl_down_sync(0xffffffffu, b, o);
    }
    __shared__ float sa[8], sb[8];
    int lane = threadIdx.x & 31, wid = threadIdx.x >> 5;
    if (lane == 0) { sa[wid] = a; sb[wid] = b; }
    __syncthreads();
    if (wid == 0) {
        int nw = blockDim.x >> 5;
        a = (lane < nw) ? sa[lane] : 0.f;
        b = (lane < nw) ? sb[lane] : 0.f;
        #pragma unroll
        for (int o = 4; o; o >>= 1) {
            a += __shfl_down_sync(0xffffffffu, a, o);
            b += __shfl_down_sync(0xffffffffu, b, o);
        }
        if (lane == 0) {
            atomicAdd(d0, (double)a);
            if (d1) atomicAdd(d1, (double)b);
        }
    }
}

__device__ __forceinline__ void block_reduce1(float a, double* d0) {
    #pragma unroll
    for (int o = 16; o; o >>= 1) a += __shfl_down_sync(0xffffffffu, a, o);
    __shared__ float sa[8];
    int lane = threadIdx.x & 31, wid = threadIdx.x >> 5;
    if (lane == 0) sa[wid] = a;
    __syncthreads();
    if (wid == 0) {
        int nw = blockDim.x >> 5;
        a = (lane < nw) ? sa[lane] : 0.f;
        #pragma unroll
        for (int o = 4; o; o >>= 1) a += __shfl_down_sync(0xffffffffu, a, o);
        if (lane == 0) atomicAdd(d0, (double)a);
    }
}

// ---------------- setup ----------------
__global__ void k_setup(const float* __restrict__ mtf) {
    int t = blockIdx.x * blockDim.x + threadIdx.x;
    if (t < NB * KS) {
        int k = t / KS, i = t - k * KS;
        g_v[t] = mtf[k * KS * KS + i * KS + KR] / sqrtf(mtf[k * KS * KS + KR * KS + KR]);
    }
    if (t < 3) g_acc[t] = 0.0;
}

// ---------------- L_spec: separable conv at sampled positions ----------------
__global__ void k_spec_h(const float* __restrict__ outp) {
    int idx = blockIdx.x * blockDim.x + threadIdx.x;
    if (idx >= BB * NB * HH * SS) return;
    int jj = idx & (SS - 1);
    int h  = (idx >> 7) & (HH - 1);
    int bk = idx >> 16;
    int k  = bk & 7;
    const float* p = outp + (long)bk * HWs + (long)h * WW;
    const float* v = g_v + k * KS;
    int col = 2 + 4 * jj;
    float s = 0.f;
    #pragma unroll
    for (int dx = 0; dx < KS; ++dx) {
        int c = col - KR + dx;
        if ((unsigned)c < (unsigned)WW) s += v[dx] * p[c];
    }
    g_sp[idx] = s;
}

__global__ void k_spec_v(const float* __restrict__ labels, const float* __restrict__ mask) {
    int idx = blockIdx.x * blockDim.x + threadIdx.x;
    float num = 0.f, den = 0.f;
    if (idx < BB * NB * SS * SS) {
        int jj = idx & 127;
        int ii = (idx >> 7) & 127;
        int bk = idx >> 14;
        int k = bk & 7, b = bk >> 3;
        int row = 2 + 4 * ii, col = 2 + 4 * jj;
        const float* v = g_v + k * KS;
        const float* sp = g_sp + (long)bk * HH * SS + jj;
        float x = 0.f;
        #pragma unroll
        for (int dy = 0; dy < KS; ++dy) {
            int r = row - KR + dy;
            if ((unsigned)r < (unsigned)HH) x += v[dy] * sp[(long)r * SS];
        }
        float y = labels[((long)(b * (NB + 1) + k) * HH + row) * WW + col];
        float m = mask[((long)k * HH + row) * WW + col];
        num = fabsf(x - y) * m;
        den = m;
    }
    block_reduce2(num, den, &g_acc[0], &g_acc[1]);
}

// ---------------- filtered pan (edge-clamped separable conv, band-0 kernel) ----------------
__global__ void k_pan_h(const float* __restrict__ inp) {
    int idx = blockIdx.x * blockDim.x + threadIdx.x;
    if (idx >= BB * HWs) return;
    int w = idx & 511, h = (idx >> 9) & 511, b = idx >> 18;
    const float* p = inp + ((long)b * (NB + 1) + NB) * HWs + (long)h * WW;
    float s = 0.f;
    #pragma unroll
    for (int dx = 0; dx < KS; ++dx) {
        int c = w - KR + dx;
        c = c < 0 ? 0 : (c > WW - 1 ? WW - 1 : c);
        s += g_v[dx] * p[c];
    }
    g_ptmp[idx] = s;
}

__global__ void k_pan_v() {
    int idx = blockIdx.x * blockDim.x + threadIdx.x;
    if (idx >= BB * HWs) return;
    int w = idx & 511, h = (idx >> 9) & 511, b = idx >> 18;
    const float* p = g_ptmp + (long)b * HWs + w;
    float s = 0.f;
    #pragma unroll
    for (int dy = 0; dy < KS; ++dy) {
        int r = h - KR + dy;
        r = r < 0 ? 0 : (r > HH - 1 ? HH - 1 : r);
        s += g_v[dy] * p[(long)r * WW];
    }
    g_panf[idx] = s;
}

// ---------------- pan-field passes (all direct-symbol) ----------------
__global__ void k_pf_row() {   // g_ptmp = rowsum16(g_panf)
    int idx = blockIdx.x * blockDim.x + threadIdx.x;
    if (idx >= BB * HWs) return;
    int w = idx & 511, h = (idx >> 9) & 511, b = idx >> 18;
    const float* p = g_panf + (long)b * HWs + (long)h * WW;
    float s = 0.f;
    #pragma unroll
    for (int t = -7; t <= 8; ++t) {
        int c = w + t;
        if ((unsigned)c < (unsigned)WW) s += p[c];
    }
    g_ptmp[idx] = s;
}

__global__ void k_pf_da() {    // g_dapf = panf - colsum16(ptmp)/256
    int idx = blockIdx.x * blockDim.x + threadIdx.x;
    if (idx >= BB * HWs) return;
    int w = idx & 511, h = (idx >> 9) & 511, b = idx >> 18;
    const float* p = g_ptmp + (long)b * HWs + w;
    float s = 0.f;
    #pragma unroll
    for (int t = -7; t <= 8; ++t) {
        int r = h + t;
        if ((unsigned)r < (unsigned)HH) s += p[(long)r * WW];
    }
    g_dapf[idx] = g_panf[idx] - s * (1.0f / 256.0f);
}

__global__ void k_pf_rowsq() { // g_ptmp = rowsum16(dapf^2)
    int idx = blockIdx.x * blockDim.x + threadIdx.x;
    if (idx >= BB * HWs) return;
    int w = idx & 511, h = (idx >> 9) & 511, b = idx >> 18;
    const float* p = g_dapf + (long)b * HWs + (long)h * WW;
    float s = 0.f;
    #pragma unroll
    for (int t = -7; t <= 8; ++t) {
        int c = w + t;
        if ((unsigned)c < (unsigned)WW) { float x = p[c]; s += x * x; }
    }
    g_ptmp[idx] = s;
}

__global__ void k_pf_saa() {   // g_saapf = colsum16(ptmp)
    int idx = blockIdx.x * blockDim.x + threadIdx.x;
    if (idx >= BB * HWs) return;
    int w = idx & 511, h = (idx >> 9) & 511, b = idx >> 18;
    const float* p = g_ptmp + (long)b * HWs + w;
    float s = 0.f;
    #pragma unroll
    for (int t = -7; t <= 8; ++t) {
        int r = h + t;
        if ((unsigned)r < (unsigned)HH) s += p[(long)r * WW];
    }
    g_saapf[idx] = s;
}

__global__ void k_lp_row(const float* __restrict__ labels) {  // g_ptmp = rowsum4(labels pan)
    int idx = blockIdx.x * blockDim.x + threadIdx.x;
    if (idx >= BB * HWs) return;
    int w = idx & 511, h = (idx >> 9) & 511, b = idx >> 18;
    const float* p = labels + ((long)b * (NB + 1) + NB) * HWs + (long)h * WW;
    float s = 0.f;
    #pragma unroll
    for (int t = -1; t <= 2; ++t) {
        int c = w + t;
        if ((unsigned)c < (unsigned)WW) s += p[c];
    }
    g_ptmp[idx] = s;
}

__global__ void k_lp_da(const float* __restrict__ labels) {   // g_dbpan = pan - colsum4(ptmp)/16
    int idx = blockIdx.x * blockDim.x + threadIdx.x;
    if (idx >= BB * HWs) return;
    int w = idx & 511, h = (idx >> 9) & 511, b = idx >> 18;
    const float* p = g_ptmp + (long)b * HWs + w;
    float s = 0.f;
    #pragma unroll
    for (int t = -1; t <= 2; ++t) {
        int r = h + t;
        if ((unsigned)r < (unsigned)HH) s += p[(long)r * WW];
    }
    float o = labels[((long)b * (NB + 1) + NB) * HWs + (long)h * WW + w];
    g_dbpan[idx] = o - s * (1.0f / 16.0f);
}

__global__ void k_lp_rowsq() { // g_ptmp = rowsum4(dbpan^2)
    int idx = blockIdx.x * blockDim.x + threadIdx.x;
    if (idx >= BB * HWs) return;
    int w = idx & 511, h = (idx >> 9) & 511, b = idx >> 18;
    const float* p = g_dbpan + (long)b * HWs + (long)h * WW;
    float s = 0.f;
    #pragma unroll
    for (int t = -1; t <= 2; ++t) {
        int c = w + t;
        if ((unsigned)c < (unsigned)WW) { float x = p[c]; s += x * x; }
    }
    g_ptmp[idx] = s;
}

__global__ void k_lp_sbb() {   // g_sbbpan = colsum4(ptmp)
    int idx = blockIdx.x * blockDim.x + threadIdx.x;
    if (idx >= BB * HWs) return;
    int w = idx & 511, h = (idx >> 9) & 511, b = idx >> 18;
    const float* p = g_ptmp + (long)b * HWs + w;
    float s = 0.f;
    #pragma unroll
    for (int t = -1; t <= 2; ++t) {
        int r = h + t;
        if ((unsigned)r < (unsigned)HH) s += p[(long)r * WW];
    }
    g_sbbpan[idx] = s;
}

// ---------------- band-field passes ----------------
__global__ void k_o_row(const float* __restrict__ outp) {  // g_bufA = rowsum4(outputs)
    int idx = blockIdx.x * blockDim.x + threadIdx.x;
    if (idx >= BB * NB * HWs) return;
    int w = idx & 511, h = (idx >> 9) & 511, img = idx >> 18;
    const float* p = outp + (long)img * HWs + (long)h * WW;
    float s = 0.f;
    #pragma unroll
    for (int t = -1; t <= 2; ++t) {
        int c = w + t;
        if ((unsigned)c < (unsigned)WW) s += p[c];
    }
    g_bufA[idx] = s;
}

__global__ void k_o_da(const float* __restrict__ outp) {   // g_bufB = outputs - colsum4(bufA)/16
    int idx = blockIdx.x * blockDim.x + threadIdx.x;
    if (idx >= BB * NB * HWs) return;
    int w = idx & 511, h = (idx >> 9) & 511, img = idx >> 18;
    const float* p = g_bufA + (long)img * HWs + w;
    float s = 0.f;
    #pragma unroll
    for (int t = -1; t <= 2; ++t) {
        int r = h + t;
        if ((unsigned)r < (unsigned)HH) s += p[(long)r * WW];
    }
    g_bufB[idx] = outp[(long)img * HWs + (long)h * WW + w] - s * (1.0f / 16.0f);
}

__global__ void k_ms_row(const float* __restrict__ inp) {  // g_bufA = rowsum16(inp bands)
    int idx = blockIdx.x * blockDim.x + threadIdx.x;
    if (idx >= BB * NB * HWs) return;
    int w = idx & 511, h = (idx >> 9) & 511, img = idx >> 18;
    int b = img >> 3, k = img & 7;
    const float* p = inp + ((long)b * (NB + 1) + k) * HWs + (long)h * WW;
    float s = 0.f;
    #pragma unroll
    for (int t = -7; t <= 8; ++t) {
        int c = w + t;
        if ((unsigned)c < (unsigned)WW) s += p[c];
    }
    g_bufA[idx] = s;
}

__global__ void k_ms_da(const float* __restrict__ inp) {   // g_bufC = inp - colsum16(bufA)/256
    int idx = blockIdx.x * blockDim.x + threadIdx.x;
    if (idx >= BB * NB * HWs) return;
    int w = idx & 511, h = (idx >> 9) & 511, img = idx >> 18;
    int b = img >> 3, k = img & 7;
    const float* p = g_bufA + (long)img * HWs + w;
    float s = 0.f;
    #pragma unroll
    for (int t = -7; t <= 8; ++t) {
        int r = h + t;
        if ((unsigned)r < (unsigned)HH) s += p[(long)r * WW];
    }
    float o = inp[((long)b * (NB + 1) + k) * HWs + (long)h * WW + w];
    g_bufC[idx] = o - s * (1.0f / 256.0f);
}

// rowsum16 of (dapf * db_ms) -> bufA ; rowsum16 of db_ms^2 -> bufD
__global__ void k_prodsq() {
    int idx = blockIdx.x * blockDim.x + threadIdx.x;
    if (idx >= BB * NB * HWs) return;
    int w = idx & 511, h = (idx >> 9) & 511, img = idx >> 18;
    int b = img >> 3;
    const float* pm = g_bufC + (long)img * HWs + (long)h * WW;
    const float* pp = g_dapf + (long)b * HWs + (long)h * WW;
    float s1 = 0.f, s2 = 0.f;
    #pragma unroll
    for (int t = -7; t <= 8; ++t) {
        int c = w + t;
        if ((unsigned)c < (unsigned)WW) {
            float m = pm[c];
            s1 += m * pp[c];
            s2 += m * m;
        }
    }
    g_bufA[idx] = s1;
    g_bufD[idx] = s2;
}

// thr = 1 - colsum16(bufA) / (sqrt(saapf * colsum16(bufD)) + eps)  -> bufC
__global__ void k_thr() {
    int idx = blockIdx.x * blockDim.x + threadIdx.x;
    if (idx >= BB * NB * HWs) return;
    int w = idx & 511, h = (idx >> 9) & 511, img = idx >> 18;
    int b = img >> 3;
    const float* a = g_bufA + (long)img * HWs + w;
    const float* d = g_bufD + (long)img * HWs + w;
    float sab = 0.f, sbb = 0.f;
    #pragma unroll
    for (int t = -7; t <= 8; ++t) {
        int r = h + t;
        if ((unsigned)r < (unsigned)HH) {
            sab += a[(long)r * WW];
            sbb += d[(long)r * WW];
        }
    }
    float saa = g_saapf[(long)b * HWs + (long)h * WW + w];
    g_bufC[idx] = 1.f - sab / (sqrtf(saa * sbb) + EPSF);
}

// final structural accumulation
__global__ void k_final() {
    int idx = blockIdx.x * blockDim.x + threadIdx.x;
    float y = 0.f;
    if (idx < BB * NB * HWs) {
        int w = idx & 511, h = (idx >> 9) & 511, img = idx >> 18;
        int b = img >> 3;
        const float* da = g_bufB + (long)img * HWs;
        const float* db = g_dbpan + (long)b * HWs;
        float sab = 0.f, saa = 0.f;
        #pragma unroll
        for (int t = -1; t <= 2; ++t) {
            int r = h + t;
            if ((unsigned)r < (unsigned)HH) {
                #pragma unroll
                for (int u = -1; u <= 2; ++u) {
                    int c = w + u;
                    if ((unsigned)c < (unsigned)WW) {
                        float A = da[(long)r * WW + c];
                        float Bv = db[(long)r * WW + c];
                        sab += A * Bv;
                        saa += A * A;
                    }
                }
            }
        }
        float sbb = g_sbbpan[(long)b * HWs + (long)h * WW + w];
        float xc = sab / (sqrtf(saa * sbb) + EPSF);
        xc = fmaxf(xc, -1.f);
        float X = 1.f - xc;
        float thr = g_bufC[idx];
        y = (X > thr) ? X : 0.f;
    }
    block_reduce1(y, &g_acc[2]);
}

__global__ void k_out(float* __restrict__ out) {
    if (threadIdx.x == 0) {
        double lspec = g_acc[0] / g_acc[1];
        double lstruct = g_acc[2] / (double)((long)BB * NB * HWs);
        out[0] = (float)(lspec + BETAD * lstruct);
    }
}

// ---------------- launch ----------------
extern "C" void kernel_launch(void* const* d_in, const int* in_sizes, int n_in,
                              void* d_out, int out_size) {
    const float* outputs = (const float*)d_in[0];  // (4,8,512,512)
    const float* labels  = (const float*)d_in[1];  // (4,9,512,512)
    const float* inp     = (const float*)d_in[2];  // (4,9,512,512)
    const float* mtf     = (const float*)d_in[3];  // (8,1,41,41)
    const float* mask    = (const float*)d_in[4];  // (1,8,512,512)
    float* out = (float*)d_out;

    const int T = 256;
    const int GP = (BB * HWs) / T;           // 4096
    const int GB = (BB * NB * HWs) / T;      // 32768

    k_setup<<<2, 256>>>(mtf);

    // L_spec
    k_spec_h<<<(BB * NB * HH * SS) / T, T>>>(outputs);
    k_spec_v<<<(BB * NB * SS * SS) / T, T>>>(labels, mask);

    // filtered pan
    k_pan_h<<<GP, T>>>(inp);
    k_pan_v<<<GP, T>>>();

    // dapf + saapf (w=8)
    k_pf_row<<<GP, T>>>();
    k_pf_da<<<GP, T>>>();
    k_pf_rowsq<<<GP, T>>>();
    k_pf_saa<<<GP, T>>>();

    // dbpan + sbbpan (w=2)
    k_lp_row<<<GP, T>>>(labels);
    k_lp_da<<<GP, T>>>(labels);
    k_lp_rowsq<<<GP, T>>>();
    k_lp_sbb<<<GP, T>>>();

    // da_out (w=2)
    k_o_row<<<GB, T>>>(outputs);
    k_o_da<<<GB, T>>>(outputs);

    // db_ms (w=8)
    k_ms_row<<<GB, T>>>(inp);
    k_ms_da<<<GB, T>>>(inp);

    // thr
    k_prodsq<<<GB, T>>>();
    k_thr<<<GB, T>>>();

    // structural term
    k_final<<<GB, T>>>();

    k_out<<<1, 32>>>(out);
    (void)in_sizes; (void)n_in; (void)out_size;
}

// round 5
// speedup vs baseline: 1.3573x; 1.3573x over previous
#include <cuda_runtime.h>

#define BB 4
#define NB 8
#define HH 512
#define WW 512
#define HWs (HH*WW)
#define KS 41
#define KR 20
#define SS 128
#define EPSF 1e-20f
#define BETAD 0.25

// ---------------- device scratch ----------------
__device__ float g_v[NB*KS];
__device__ float g_sp[BB*NB*HH*SS];
__device__ float g_panf[BB*HWs];
__device__ float g_dapf[BB*HWs];
__device__ float g_saapf[BB*HWs];
__device__ float g_dbpan[BB*HWs];
__device__ float g_sbbpan[BB*HWs];
__device__ float g_thr[BB*NB*HWs];
__device__ double g_acc[3];

// ---------------- reduction helpers ----------------
__device__ __forceinline__ void block_reduce2(float a, float b, double* d0, double* d1) {
    #pragma unroll
    for (int o = 16; o; o >>= 1) {
        a += __shfl_down_sync(0xffffffffu, a, o);
        b += __shfl_down_sync(0xffffffffu, b, o);
    }
    __shared__ float sa[8], sb[8];
    int lane = threadIdx.x & 31, wid = threadIdx.x >> 5;
    if (lane == 0) { sa[wid] = a; sb[wid] = b; }
    __syncthreads();
    if (wid == 0) {
        int nw = blockDim.x >> 5;
        a = (lane < nw) ? sa[lane] : 0.f;
        b = (lane < nw) ? sb[lane] : 0.f;
        #pragma unroll
        for (int o = 4; o; o >>= 1) {
            a += __shfl_down_sync(0xffffffffu, a, o);
            b += __shfl_down_sync(0xffffffffu, b, o);
        }
        if (lane == 0) { atomicAdd(d0, (double)a); atomicAdd(d1, (double)b); }
    }
}

__device__ __forceinline__ void block_reduce1(float a, double* d0) {
    #pragma unroll
    for (int o = 16; o; o >>= 1) a += __shfl_down_sync(0xffffffffu, a, o);
    __shared__ float sa[8];
    int lane = threadIdx.x & 31, wid = threadIdx.x >> 5;
    if (lane == 0) sa[wid] = a;
    __syncthreads();
    if (wid == 0) {
        int nw = blockDim.x >> 5;
        a = (lane < nw) ? sa[lane] : 0.f;
        #pragma unroll
        for (int o = 4; o; o >>= 1) a += __shfl_down_sync(0xffffffffu, a, o);
        if (lane == 0) atomicAdd(d0, (double)a);
    }
}

// ---------------- setup ----------------
__global__ void k_setup(const float* __restrict__ mtf) {
    int t = blockIdx.x * blockDim.x + threadIdx.x;
    if (t < NB * KS) {
        int k = t / KS, i = t - k * KS;
        g_v[t] = mtf[k * KS * KS + i * KS + KR] / sqrtf(mtf[k * KS * KS + KR * KS + KR]);
    }
    if (t < 3) g_acc[t] = 0.0;
}

// ---------------- L_spec horizontal conv (smem row cache) ----------------
__global__ void k_spec_h(const float* __restrict__ outp) {
    int hp = blockIdx.x & 255;
    int bk = blockIdx.x >> 8;
    int k  = bk & 7;
    __shared__ float s_row[2][552];
    __shared__ float s_v[KS];
    int t = threadIdx.x;
    if (t < KS) s_v[t] = g_v[k * KS + t];
    if (t < 80) { int r = t / 40, p = t % 40; s_row[r][p < 20 ? p : p + 512] = 0.f; }
    const float* src = outp + (long)bk * HWs + (long)(2 * hp) * WW;
    for (int i = t; i < 1024; i += 256) {
        int r = i >> 9, c = i & 511;
        s_row[r][20 + c] = src[r * WW + c];
    }
    __syncthreads();
    int r = t >> 7, jj = t & 127;
    int col = 2 + 4 * jj;
    float s = 0.f;
    #pragma unroll
    for (int d = 0; d < KS; ++d) s += s_v[d] * s_row[r][col + d];
    g_sp[((long)bk * HH + 2 * hp + r) * SS + jj] = s;
}

// ---------------- L_spec vertical + reduce ----------------
__global__ void k_spec_v(const float* __restrict__ labels, const float* __restrict__ mask) {
    int idx = blockIdx.x * blockDim.x + threadIdx.x;
    float num = 0.f, den = 0.f;
    if (idx < BB * NB * SS * SS) {
        int jj = idx & 127;
        int ii = (idx >> 7) & 127;
        int bk = idx >> 14;
        int k = bk & 7, b = bk >> 3;
        int row = 2 + 4 * ii, col = 2 + 4 * jj;
        const float* v = g_v + k * KS;
        const float* sp = g_sp + (long)bk * HH * SS + jj;
        float x = 0.f;
        #pragma unroll
        for (int dy = 0; dy < KS; ++dy) {
            int r = row - KR + dy;
            if ((unsigned)r < (unsigned)HH) x += v[dy] * sp[(long)r * SS];
        }
        float y = labels[((long)(b * (NB + 1) + k) * HH + row) * WW + col];
        float m = mask[((long)k * HH + row) * WW + col];
        num = fabsf(x - y) * m;
        den = m;
    }
    block_reduce2(num, den, &g_acc[0], &g_acc[1]);
}

// ---------------- fused pan conv (edge-clamped, separable, band-0) ----------------
__global__ void k_pan_conv(const float* __restrict__ inp) {
    int b = blockIdx.y;
    int x0 = (blockIdx.x & 15) << 5, y0 = (blockIdx.x >> 4) << 5;
    __shared__ float s_in[72][73];
    __shared__ float s_mid[72][33];
    const float* src = inp + ((long)b * (NB + 1) + NB) * HWs;
    int t = threadIdx.x;
    for (int i = t; i < 72 * 72; i += 256) {
        int r = i / 72, c = i - r * 72;
        int gr = y0 + r - 20; gr = gr < 0 ? 0 : (gr > 511 ? 511 : gr);
        int gc = x0 + c - 20; gc = gc < 0 ? 0 : (gc > 511 ? 511 : gc);
        s_in[r][c] = src[gr * WW + gc];
    }
    __syncthreads();
    for (int i = t; i < 72 * 32; i += 256) {
        int r = i >> 5, c = i & 31;
        float s = 0.f;
        #pragma unroll
        for (int d = 0; d < KS; ++d) s += g_v[d] * s_in[r][c + d];
        s_mid[r][c] = s;
    }
    __syncthreads();
    for (int i = t; i < 1024; i += 256) {
        int r = i >> 5, c = i & 31;
        float s = 0.f;
        #pragma unroll
        for (int d = 0; d < KS; ++d) s += g_v[d] * s_mid[r + d][c];
        g_panf[((long)b << 18) + (long)(y0 + r) * WW + x0 + c] = s;
    }
}

// ---------------- fused pan stats: dapf (w=8) + saapf ----------------
__global__ void k_pan_stats() {
    int b = blockIdx.y;
    int x0 = (blockIdx.x & 15) << 5, y0 = (blockIdx.x >> 4) << 5;
    __shared__ float s_pf[64][65];
    __shared__ float s_rs[64][49];
    __shared__ float s_da[48][49];
    __shared__ float s_q[48][33];
    const float* src = g_panf + ((long)b << 18);
    int t = threadIdx.x;
    for (int i = t; i < 64 * 64; i += 256) {
        int r = i >> 6, c = i & 63;
        int gr = y0 + r - 15, gc = x0 + c - 15;
        s_pf[r][c] = ((unsigned)gr < 512u && (unsigned)gc < 512u) ? src[gr * WW + gc] : 0.f;
    }
    __syncthreads();
    for (int i = t; i < 64 * 48; i += 256) {
        int r = i / 48, j = i - r * 48;
        float s = 0.f;
        #pragma unroll
        for (int u = 1; u <= 16; ++u) s += s_pf[r][j + u];
        s_rs[r][j] = s;
    }
    __syncthreads();
    for (int i = t; i < 48 * 48; i += 256) {
        int ii = i / 48, j = i - ii * 48;
        float s = 0.f;
        #pragma unroll
        for (int u = 1; u <= 16; ++u) s += s_rs[ii + u][j];
        int gr = y0 + ii - 7, gc = x0 + j - 7;
        bool in = ((unsigned)gr < 512u) && ((unsigned)gc < 512u);
        float d = in ? (s_pf[ii + 8][j + 8] - s * (1.0f / 256.0f)) : 0.f;
        s_da[ii][j] = d;
        if (ii >= 7 && ii < 39 && j >= 7 && j < 39)
            g_dapf[((long)b << 18) + (long)gr * WW + gc] = d;
    }
    __syncthreads();
    for (int i = t; i < 48 * 32; i += 256) {
        int r = i >> 5, w = i & 31;
        float s = 0.f;
        #pragma unroll
        for (int u = 0; u < 16; ++u) { float x = s_da[r][w + u]; s += x * x; }
        s_q[r][w] = s;
    }
    __syncthreads();
    for (int i = t; i < 1024; i += 256) {
        int oy = i >> 5, ox = i & 31;
        float s = 0.f;
        #pragma unroll
        for (int u = 0; u < 16; ++u) s += s_q[oy + u][ox];
        g_saapf[((long)b << 18) + (long)(y0 + oy) * WW + x0 + ox] = s;
    }
}

// ---------------- fused label-pan stats: dbpan (w=2) + sbbpan ----------------
__global__ void k_lab_stats(const float* __restrict__ labels) {
    int b = blockIdx.y;
    int x0 = (blockIdx.x & 15) << 5, y0 = (blockIdx.x >> 4) << 5;
    __shared__ float s_lb[40][41];
    __shared__ float s_rs[40][37];
    __shared__ float s_db[36][37];
    __shared__ float s_q[36][33];
    const float* src = labels + ((long)b * (NB + 1) + NB) * HWs;
    int t = threadIdx.x;
    for (int i = t; i < 40 * 40; i += 256) {
        int r = i / 40, c = i - r * 40;
        int gr = y0 + r - 3, gc = x0 + c - 3;
        s_lb[r][c] = ((unsigned)gr < 512u && (unsigned)gc < 512u) ? src[gr * WW + gc] : 0.f;
    }
    __syncthreads();
    for (int i = t; i < 40 * 36; i += 256) {
        int r = i / 36, j = i - r * 36;
        float s = 0.f;
        #pragma unroll
        for (int u = 2; u <= 5; ++u) s += s_lb[r][j + u];
        s_rs[r][j] = s;
    }
    __syncthreads();
    for (int i = t; i < 36 * 36; i += 256) {
        int ii = i / 36, j = i - ii * 36;
        float s = 0.f;
        #pragma unroll
        for (int u = 1; u <= 4; ++u) s += s_rs[ii + u][j];
        int gr = y0 + ii - 1, gc = x0 + j - 1;
        bool in = ((unsigned)gr < 512u) && ((unsigned)gc < 512u);
        float d = in ? (s_lb[ii + 2][j + 2] - s * (1.0f / 16.0f)) : 0.f;
        s_db[ii][j] = d;
        if (ii >= 1 && ii < 33 && j >= 1 && j < 33)
            g_dbpan[((long)b << 18) + (long)gr * WW + gc] = d;
    }
    __syncthreads();
    for (int i = t; i < 36 * 32; i += 256) {
        int r = i >> 5, w = i & 31;
        float s = 0.f;
        #pragma unroll
        for (int u = 0; u < 4; ++u) { float x = s_db[r][w + u]; s += x * x; }
        s_q[r][w] = s;
    }
    __syncthreads();
    for (int i = t; i < 1024; i += 256) {
        int oy = i >> 5, ox = i & 31;
        float s = 0.f;
        #pragma unroll
        for (int u = 0; u < 4; ++u) s += s_q[oy + u][ox];
        g_sbbpan[((long)b << 18) + (long)(y0 + oy) * WW + x0 + ox] = s;
    }
}

// ---------------- fused thr: db_ms (w=8) -> xcorr(dapf, db_ms) -> thr ----------------
__global__ void k_thr_fused(const float* __restrict__ inp) {
    int img = blockIdx.y;
    int b = img >> 3, k = img & 7;
    int x0 = (blockIdx.x & 15) << 5, y0 = (blockIdx.x >> 4) << 5;
    __shared__ float B[9648];
    float* s_in = B;                 // 64 x 65
    float* s_rs = B + 4160;          // 64 x 49
    float* s_db = B + 7296;          // 48 x 49
    const float* src = inp + ((long)b * (NB + 1) + k) * HWs;
    int t = threadIdx.x;
    for (int i = t; i < 64 * 64; i += 256) {
        int r = i >> 6, c = i & 63;
        int gr = y0 + r - 15, gc = x0 + c - 15;
        s_in[r * 65 + c] = ((unsigned)gr < 512u && (unsigned)gc < 512u) ? src[gr * WW + gc] : 0.f;
    }
    __syncthreads();
    {
        int r = t >> 2, j0 = (t & 3) * 12;
        const float* row = s_in + r * 65;
        float s = 0.f;
        #pragma unroll
        for (int u = 1; u <= 16; ++u) s += row[j0 + u];
        s_rs[r * 49 + j0] = s;
        #pragma unroll
        for (int j = 1; j < 12; ++j) {
            s += row[j0 + j + 16] - row[j0 + j];
            s_rs[r * 49 + j0 + j] = s;
        }
    }
    __syncthreads();
    if (t < 192) {
        int j = t >> 2, i0 = (t & 3) * 12;
        int gc = x0 + j - 7;
        bool cin = (unsigned)gc < 512u;
        float s = 0.f;
        #pragma unroll
        for (int u = 1; u <= 16; ++u) s += s_rs[(i0 + u) * 49 + j];
        {
            int gr = y0 + i0 - 7;
            bool in = cin && ((unsigned)gr < 512u);
            s_db[i0 * 49 + j] = in ? (s_in[(i0 + 8) * 65 + j + 8] - s * (1.0f / 256.0f)) : 0.f;
        }
        #pragma unroll
        for (int ii = 1; ii < 12; ++ii) {
            s += s_rs[(i0 + ii + 16) * 49 + j] - s_rs[(i0 + ii) * 49 + j];
            int gr = y0 + i0 + ii - 7;
            bool in = cin && ((unsigned)gr < 512u);
            s_db[(i0 + ii) * 49 + j] = in ? (s_in[(i0 + ii + 8) * 65 + j + 8] - s * (1.0f / 256.0f)) : 0.f;
        }
    }
    __syncthreads();
    float* s_pf = B;                 // 48 x 49
    float* s_e  = B + 2352;          // 48 x 33
    float* s_f  = B + 3936;          // 48 x 33
    const float* pfsrc = g_dapf + ((long)b << 18);
    for (int i = t; i < 48 * 48; i += 256) {
        int r = i / 48, c = i - r * 48;
        int gr = y0 + r - 7, gc = x0 + c - 7;
        s_pf[r * 49 + c] = ((unsigned)gr < 512u && (unsigned)gc < 512u) ? pfsrc[gr * WW + gc] : 0.f;
    }
    __syncthreads();
    if (t < 192) {
        int r = t >> 2, w0 = (t & 3) * 8;
        const float* dbr = s_db + r * 49;
        const float* pfr = s_pf + r * 49;
        float se = 0.f, sf = 0.f;
        #pragma unroll
        for (int u = 0; u < 16; ++u) {
            float d = dbr[w0 + u], p = pfr[w0 + u];
            se += d * p; sf += d * d;
        }
        s_e[r * 33 + w0] = se; s_f[r * 33 + w0] = sf;
        #pragma unroll
        for (int w = 1; w < 8; ++w) {
            float d1 = dbr[w0 + w + 15], p1 = pfr[w0 + w + 15];
            float d0 = dbr[w0 + w - 1],  p0 = pfr[w0 + w - 1];
            se += d1 * p1 - d0 * p0;
            sf += d1 * d1 - d0 * d0;
            s_e[r * 33 + w0 + w] = se; s_f[r * 33 + w0 + w] = sf;
        }
    }
    __syncthreads();
    const float* saab = g_saapf + ((long)b << 18);
    float* dst = g_thr + (long)img * HWs;
    for (int i = t; i < 1024; i += 256) {
        int oy = i >> 5, ox = i & 31;
        float sab = 0.f, sbb = 0.f;
        #pragma unroll
        for (int u = 0; u < 16; ++u) {
            sab += s_e[(oy + u) * 33 + ox];
            sbb += s_f[(oy + u) * 33 + ox];
        }
        float saa = saab[(long)(y0 + oy) * WW + x0 + ox];
        dst[(long)(y0 + oy) * WW + x0 + ox] = 1.f - sab / (sqrtf(saa * sbb) + EPSF);
    }
}

// ---------------- fused final: da_out (w=2) -> xcorr(out, pan, 2) -> masked mean ----------------
__global__ void k_final_fused(const float* __restrict__ outp) {
    int img = blockIdx.y;
    int b = img >> 3;
    int x0 = (blockIdx.x & 15) << 5, y0 = (blockIdx.x >> 4) << 5;
    __shared__ float s_out[40][41];
    __shared__ float s_rs[40][37];
    __shared__ float s_da[36][37];
    __shared__ float s_dbp[36][37];
    __shared__ float s_e[36][33];
    __shared__ float s_f[36][33];
    const float* src = outp + (long)img * HWs;
    int t = threadIdx.x;
    for (int i = t; i < 40 * 40; i += 256) {
        int r = i / 40, c = i - r * 40;
        int gr = y0 + r - 3, gc = x0 + c - 3;
        s_out[r][c] = ((unsigned)gr < 512u && (unsigned)gc < 512u) ? src[gr * WW + gc] : 0.f;
    }
    const float* dbsrc = g_dbpan + ((long)b << 18);
    for (int i = t; i < 36 * 36; i += 256) {
        int r = i / 36, c = i - r * 36;
        int gr = y0 + r - 1, gc = x0 + c - 1;
        s_dbp[r][c] = ((unsigned)gr < 512u && (unsigned)gc < 512u) ? dbsrc[gr * WW + gc] : 0.f;
    }
    __syncthreads();
    for (int i = t; i < 40 * 36; i += 256) {
        int r = i / 36, j = i - r * 36;
        float s = 0.f;
        #pragma unroll
        for (int u = 2; u <= 5; ++u) s += s_out[r][j + u];
        s_rs[r][j] = s;
    }
    __syncthreads();
    for (int i = t; i < 36 * 36; i += 256) {
        int ii = i / 36, j = i - ii * 36;
        float s = 0.f;
        #pragma unroll
        for (int u = 1; u <= 4; ++u) s += s_rs[ii + u][j];
        int gr = y0 + ii - 1, gc = x0 + j - 1;
        bool in = ((unsigned)gr < 512u) && ((unsigned)gc < 512u);
        s_da[ii][j] = in ? (s_out[ii + 2][j + 2] - s * (1.0f / 16.0f)) : 0.f;
    }
    __syncthreads();
    for (int i = t; i < 36 * 32; i += 256) {
        int r = i >> 5, w = i & 31;
        float se = 0.f, sf = 0.f;
        #pragma unroll
        for (int u = 0; u < 4; ++u) {
            float A = s_da[r][w + u], Bv = s_dbp[r][w + u];
            se += A * Bv; sf += A * A;
        }
        s_e[r][w] = se; s_f[r][w] = sf;
    }
    __syncthreads();
    const float* sbbb = g_sbbpan + ((long)b << 18);
    const float* thrb = g_thr + (long)img * HWs;
    float acc = 0.f;
    for (int i = t; i < 1024; i += 256) {
        int oy = i >> 5, ox = i & 31;
        float sab = 0.f, saa = 0.f;
        #pragma unroll
        for (int u = 0; u < 4; ++u) {
            sab += s_e[oy + u][ox];
            saa += s_f[oy + u][ox];
        }
        float sbb = sbbb[(long)(y0 + oy) * WW + x0 + ox];
        float xc = sab / (sqrtf(saa * sbb) + EPSF);
        xc = fmaxf(xc, -1.f);
        float X = 1.f - xc;
        float thr = thrb[(long)(y0 + oy) * WW + x0 + ox];
        acc += (X > thr) ? X : 0.f;
    }
    block_reduce1(acc, &g_acc[2]);
}

__global__ void k_out(float* __restrict__ out) {
    if (threadIdx.x == 0) {
        double lspec = g_acc[0] / g_acc[1];
        double lstruct = g_acc[2] / (double)((long)BB * NB * HWs);
        out[0] = (float)(lspec + BETAD * lstruct);
    }
}

// ---------------- launch ----------------
extern "C" void kernel_launch(void* const* d_in, const int* in_sizes, int n_in,
                              void* d_out, int out_size) {
    const float* outputs = (const float*)d_in[0];
    const float* labels  = (const float*)d_in[1];
    const float* inp     = (const float*)d_in[2];
    const float* mtf     = (const float*)d_in[3];
    const float* mask    = (const float*)d_in[4];
    float* out = (float*)d_out;

    k_setup<<<2, 256>>>(mtf);
    k_spec_h<<<BB * NB * 256, 256>>>(outputs);
    k_spec_v<<<(BB * NB * SS * SS) / 256, 256>>>(labels, mask);
    k_pan_conv<<<dim3(256, BB), 256>>>(inp);
    k_pan_stats<<<dim3(256, BB), 256>>>();
    k_lab_stats<<<dim3(256, BB), 256>>>(labels);
    k_thr_fused<<<dim3(256, BB * NB), 256>>>(inp);
    k_final_fused<<<dim3(256, BB * NB), 256>>>(outputs);
    k_out<<<1, 32>>>(out);
    (void)in_sizes; (void)n_in; (void)out_size;
}

// round 6
// speedup vs baseline: 1.5118x; 1.1138x over previous
#include <cuda_runtime.h>

#define BB 4
#define NB 8
#define HH 512
#define WW 512
#define HWs (HH*WW)
#define KS 41
#define KR 20
#define SS 128
#define EPSF 1e-20f
#define BETAD 0.25

// ---------------- device scratch ----------------
__device__ float g_v[NB*KS];
__device__ float g_sp[BB*NB*HH*SS];
__device__ float g_panf[BB*HWs];
__device__ float g_dapf[BB*HWs];
__device__ float g_saapf[BB*HWs];
__device__ float g_dbpan[BB*HWs];
__device__ float g_sbbpan[BB*HWs];
__device__ double g_acc[3];

// ---------------- reduction helpers ----------------
__device__ __forceinline__ void block_reduce2(float a, float b, double* d0, double* d1) {
    #pragma unroll
    for (int o = 16; o; o >>= 1) {
        a += __shfl_down_sync(0xffffffffu, a, o);
        b += __shfl_down_sync(0xffffffffu, b, o);
    }
    __shared__ float sa[8], sb[8];
    int lane = threadIdx.x & 31, wid = threadIdx.x >> 5;
    if (lane == 0) { sa[wid] = a; sb[wid] = b; }
    __syncthreads();
    if (wid == 0) {
        int nw = blockDim.x >> 5;
        a = (lane < nw) ? sa[lane] : 0.f;
        b = (lane < nw) ? sb[lane] : 0.f;
        #pragma unroll
        for (int o = 4; o; o >>= 1) {
            a += __shfl_down_sync(0xffffffffu, a, o);
            b += __shfl_down_sync(0xffffffffu, b, o);
        }
        if (lane == 0) { atomicAdd(d0, (double)a); atomicAdd(d1, (double)b); }
    }
}

__device__ __forceinline__ void block_reduce1(float a, double* d0) {
    #pragma unroll
    for (int o = 16; o; o >>= 1) a += __shfl_down_sync(0xffffffffu, a, o);
    __shared__ float sa[8];
    int lane = threadIdx.x & 31, wid = threadIdx.x >> 5;
    if (lane == 0) sa[wid] = a;
    __syncthreads();
    if (wid == 0) {
        int nw = blockDim.x >> 5;
        a = (lane < nw) ? sa[lane] : 0.f;
        #pragma unroll
        for (int o = 4; o; o >>= 1) a += __shfl_down_sync(0xffffffffu, a, o);
        if (lane == 0) atomicAdd(d0, (double)a);
    }
}

// ---------------- setup ----------------
__global__ void k_setup(const float* __restrict__ mtf) {
    int t = blockIdx.x * blockDim.x + threadIdx.x;
    if (t < NB * KS) {
        int k = t / KS, i = t - k * KS;
        g_v[t] = mtf[k * KS * KS + i * KS + KR] / sqrtf(mtf[k * KS * KS + KR * KS + KR]);
    }
    if (t < 3) g_acc[t] = 0.0;
}

// ---------------- L_spec horizontal conv: float4 rolling window ----------------
__global__ void __launch_bounds__(256) k_spec_h(const float* __restrict__ outp) {
    int hp = blockIdx.x & 255;
    int bk = blockIdx.x >> 8;
    int k  = bk & 7;
    __shared__ __align__(16) float s_row[2][556];
    __shared__ float s_v[44];
    int t = threadIdx.x;
    if (t < 44) s_v[t] = (t < KS) ? g_v[k * KS + t] : 0.f;
    if (t < 88) { int r = t / 44, p = t % 44; s_row[r][p < 22 ? p : p - 22 + 534] = 0.f; }
    const float* src = outp + (long)bk * HWs + (long)(2 * hp) * WW;
    for (int i = t; i < 1024; i += 256) {
        int r = i >> 9, c = i & 511;
        s_row[r][22 + c] = src[r * WW + c];
    }
    __syncthreads();
    int r = t >> 7, jj = t & 127;
    const float4* row4 = reinterpret_cast<const float4*>(s_row[r]) + (jj + 1);
    float4 cur = row4[0];
    float s = 0.f;
    #pragma unroll
    for (int tt = 0; tt < 10; ++tt) {
        float4 nxt = row4[tt + 1];
        s += s_v[4*tt] * cur.x + s_v[4*tt+1] * cur.y + s_v[4*tt+2] * cur.z + s_v[4*tt+3] * cur.w;
        cur = nxt;
    }
    s += s_v[40] * cur.x;
    g_sp[((long)bk * HH + 2 * hp + r) * SS + jj] = s;
}

// ---------------- L_spec vertical: smem tile, 4 outputs/thread ----------------
__global__ void __launch_bounds__(256) k_spec_v(const float* __restrict__ labels, const float* __restrict__ mask) {
    int bk = blockIdx.y;
    int kb = bk & 7, b = bk >> 3;
    int ii0 = blockIdx.x * 8;
    __shared__ float s_sp[69][128];
    __shared__ float s_v[KS];
    int t = threadIdx.x;
    if (t < KS) s_v[t] = g_v[kb * KS + t];
    const float* spb = g_sp + (long)bk * HH * SS;
    for (int i = t; i < 69 * 128; i += 256) {
        int m = i >> 7, jj = i & 127;
        int gr = 4 * ii0 - 18 + m;
        s_sp[m][jj] = ((unsigned)gr < 512u) ? spb[(long)gr * SS + jj] : 0.f;
    }
    __syncthreads();
    int jj = t & 127, half = t >> 7;
    int base = 16 * half;
    float o0 = 0.f, o1 = 0.f, o2 = 0.f, o3 = 0.f;
    #pragma unroll
    for (int m = 0; m < 53; ++m) {
        float x = s_sp[base + m][jj];
        if (m <= 40) o0 += s_v[m] * x;
        if (m >= 4 && m <= 44) o1 += s_v[m - 4] * x;
        if (m >= 8 && m <= 48) o2 += s_v[m - 8] * x;
        if (m >= 12) o3 += s_v[m - 12] * x;
    }
    float xs[4] = {o0, o1, o2, o3};
    float num = 0.f, den = 0.f;
    #pragma unroll
    for (int q = 0; q < 4; ++q) {
        int ii = ii0 + 4 * half + q;
        int row = 2 + 4 * ii, col = 2 + 4 * jj;
        float y = labels[((long)(b * (NB + 1) + kb) * HH + row) * WW + col];
        float m2 = mask[((long)kb * HH + row) * WW + col];
        num += fabsf(xs[q] - y) * m2;
        den += m2;
    }
    block_reduce2(num, den, &g_acc[0], &g_acc[1]);
}

// ---------------- fused pan conv: float4 rolling h-phase, 4-out/thread v-phase ----------------
__global__ void __launch_bounds__(256) k_pan_conv(const float* __restrict__ inp) {
    int b = blockIdx.y;
    int x0 = (blockIdx.x & 15) << 5, y0 = (blockIdx.x >> 4) << 5;
    __shared__ __align__(16) float s_in[72 * 76];
    __shared__ float s_mid[72 * 33];
    __shared__ float s_v[44];
    const float* src = inp + ((long)b * (NB + 1) + NB) * HWs;
    int t = threadIdx.x;
    if (t < 44) s_v[t] = (t < KS) ? g_v[t] : 0.f;
    for (int i = t; i < 72 * 72; i += 256) {
        int r = i / 72, c = i - r * 72;
        int gr = y0 + r - 20; gr = gr < 0 ? 0 : (gr > 511 ? 511 : gr);
        int gc = x0 + c - 20; gc = gc < 0 ? 0 : (gc > 511 ? 511 : gc);
        s_in[r * 76 + c] = src[gr * WW + gc];
    }
    __syncthreads();
    // h-phase: 72 rows x 8 col-groups of 4
    for (int i = t; i < 576; i += 256) {
        int r = i >> 3, cg = i & 7;
        const float4* row4 = reinterpret_cast<const float4*>(s_in + r * 76) + cg;
        float o0 = 0.f, o1 = 0.f, o2 = 0.f, o3 = 0.f;
        float4 cur = row4[0];
        #pragma unroll
        for (int tt = 0; tt < 10; ++tt) {
            float4 nxt = row4[tt + 1];
            float v0 = s_v[4*tt], v1 = s_v[4*tt+1], v2 = s_v[4*tt+2], v3 = s_v[4*tt+3];
            o0 += v0 * cur.x + v1 * cur.y + v2 * cur.z + v3 * cur.w;
            o1 += v0 * cur.y + v1 * cur.z + v2 * cur.w + v3 * nxt.x;
            o2 += v0 * cur.z + v1 * cur.w + v2 * nxt.x + v3 * nxt.y;
            o3 += v0 * cur.w + v1 * nxt.x + v2 * nxt.y + v3 * nxt.z;
            cur = nxt;
        }
        float v40 = s_v[40];
        o0 += v40 * cur.x; o1 += v40 * cur.y; o2 += v40 * cur.z; o3 += v40 * cur.w;
        float* dst = s_mid + r * 33 + 4 * cg;
        dst[0] = o0; dst[1] = o1; dst[2] = o2; dst[3] = o3;
    }
    __syncthreads();
    // v-phase: 8 row-groups of 4 x 32 cols
    {
        int rg = t >> 5, c = t & 31, r0 = rg * 4;
        float o0 = 0.f, o1 = 0.f, o2 = 0.f, o3 = 0.f;
        #pragma unroll
        for (int m = 0; m < 44; ++m) {
            float x = s_mid[(r0 + m) * 33 + c];
            if (m <= 40) o0 += s_v[m] * x;
            if (m >= 1 && m <= 41) o1 += s_v[m - 1] * x;
            if (m >= 2 && m <= 42) o2 += s_v[m - 2] * x;
            if (m >= 3) o3 += s_v[m - 3] * x;
        }
        float* dst = g_panf + ((long)b << 18) + (long)(y0 + r0) * WW + x0 + c;
        dst[0] = o0; dst[WW] = o1; dst[2 * WW] = o2; dst[3 * WW] = o3;
    }
}

// ---------------- fused pan stats: dapf (w=8) + saapf ----------------
__global__ void __launch_bounds__(256) k_pan_stats() {
    int b = blockIdx.y;
    int x0 = (blockIdx.x & 15) << 5, y0 = (blockIdx.x >> 4) << 5;
    __shared__ float s_pf[64][65];
    __shared__ float s_rs[64][49];
    __shared__ float s_da[48][49];
    __shared__ float s_q[48][33];
    const float* src = g_panf + ((long)b << 18);
    int t = threadIdx.x;
    for (int i = t; i < 64 * 64; i += 256) {
        int r = i >> 6, c = i & 63;
        int gr = y0 + r - 15, gc = x0 + c - 15;
        s_pf[r][c] = ((unsigned)gr < 512u && (unsigned)gc < 512u) ? src[gr * WW + gc] : 0.f;
    }
    __syncthreads();
    for (int i = t; i < 64 * 48; i += 256) {
        int r = i / 48, j = i - r * 48;
        float s = 0.f;
        #pragma unroll
        for (int u = 1; u <= 16; ++u) s += s_pf[r][j + u];
        s_rs[r][j] = s;
    }
    __syncthreads();
    for (int i = t; i < 48 * 48; i += 256) {
        int ii = i / 48, j = i - ii * 48;
        float s = 0.f;
        #pragma unroll
        for (int u = 1; u <= 16; ++u) s += s_rs[ii + u][j];
        int gr = y0 + ii - 7, gc = x0 + j - 7;
        bool in = ((unsigned)gr < 512u) && ((unsigned)gc < 512u);
        float d = in ? (s_pf[ii + 8][j + 8] - s * (1.0f / 256.0f)) : 0.f;
        s_da[ii][j] = d;
        if (ii >= 7 && ii < 39 && j >= 7 && j < 39)
            g_dapf[((long)b << 18) + (long)gr * WW + gc] = d;
    }
    __syncthreads();
    for (int i = t; i < 48 * 32; i += 256) {
        int r = i >> 5, w = i & 31;
        float s = 0.f;
        #pragma unroll
        for (int u = 0; u < 16; ++u) { float x = s_da[r][w + u]; s += x * x; }
        s_q[r][w] = s;
    }
    __syncthreads();
    for (int i = t; i < 1024; i += 256) {
        int oy = i >> 5, ox = i & 31;
        float s = 0.f;
        #pragma unroll
        for (int u = 0; u < 16; ++u) s += s_q[oy + u][ox];
        g_saapf[((long)b << 18) + (long)(y0 + oy) * WW + x0 + ox] = s;
    }
}

// ---------------- fused label-pan stats: dbpan (w=2) + sbbpan ----------------
__global__ void __launch_bounds__(256) k_lab_stats(const float* __restrict__ labels) {
    int b = blockIdx.y;
    int x0 = (blockIdx.x & 15) << 5, y0 = (blockIdx.x >> 4) << 5;
    __shared__ float s_lb[40][41];
    __shared__ float s_rs[40][37];
    __shared__ float s_db[36][37];
    __shared__ float s_q[36][33];
    const float* src = labels + ((long)b * (NB + 1) + NB) * HWs;
    int t = threadIdx.x;
    for (int i = t; i < 40 * 40; i += 256) {
        int r = i / 40, c = i - r * 40;
        int gr = y0 + r - 3, gc = x0 + c - 3;
        s_lb[r][c] = ((unsigned)gr < 512u && (unsigned)gc < 512u) ? src[gr * WW + gc] : 0.f;
    }
    __syncthreads();
    for (int i = t; i < 40 * 36; i += 256) {
        int r = i / 36, j = i - r * 36;
        float s = 0.f;
        #pragma unroll
        for (int u = 2; u <= 5; ++u) s += s_lb[r][j + u];
        s_rs[r][j] = s;
    }
    __syncthreads();
    for (int i = t; i < 36 * 36; i += 256) {
        int ii = i / 36, j = i - ii * 36;
        float s = 0.f;
        #pragma unroll
        for (int u = 1; u <= 4; ++u) s += s_rs[ii + u][j];
        int gr = y0 + ii - 1, gc = x0 + j - 1;
        bool in = ((unsigned)gr < 512u) && ((unsigned)gc < 512u);
        float d = in ? (s_lb[ii + 2][j + 2] - s * (1.0f / 16.0f)) : 0.f;
        s_db[ii][j] = d;
        if (ii >= 1 && ii < 33 && j >= 1 && j < 33)
            g_dbpan[((long)b << 18) + (long)gr * WW + gc] = d;
    }
    __syncthreads();
    for (int i = t; i < 36 * 32; i += 256) {
        int r = i >> 5, w = i & 31;
        float s = 0.f;
        #pragma unroll
        for (int u = 0; u < 4; ++u) { float x = s_db[r][w + u]; s += x * x; }
        s_q[r][w] = s;
    }
    __syncthreads();
    for (int i = t; i < 1024; i += 256) {
        int oy = i >> 5, ox = i & 31;
        float s = 0.f;
        #pragma unroll
        for (int u = 0; u < 4; ++u) s += s_q[oy + u][ox];
        g_sbbpan[((long)b << 18) + (long)(y0 + oy) * WW + x0 + ox] = s;
    }
}

// ---------------- fused structural: thr + final in one kernel, thr kept in smem ----------------
__global__ void __launch_bounds__(256) k_struct(const float* __restrict__ inp, const float* __restrict__ outp) {
    int img = blockIdx.y;
    int b = img >> 3, kb = img & 7;
    int x0 = (blockIdx.x & 15) << 5, y0 = (blockIdx.x >> 4) << 5;
    __shared__ float B[10672];
    float* s_thr = B + 9648;         // 32 x 32 (persists)
    int t = threadIdx.x;
    // ===== thr part =====
    {
        float* s_in = B;             // 64 x 65
        float* s_rs = B + 4160;      // 64 x 49
        float* s_db = B + 7296;      // 48 x 49
        const float* src = inp + ((long)b * (NB + 1) + kb) * HWs;
        for (int i = t; i < 64 * 64; i += 256) {
            int r = i >> 6, c = i & 63;
            int gr = y0 + r - 15, gc = x0 + c - 15;
            s_in[r * 65 + c] = ((unsigned)gr < 512u && (unsigned)gc < 512u) ? src[gr * WW + gc] : 0.f;
        }
        __syncthreads();
        {
            int r = t >> 2, j0 = (t & 3) * 12;
            const float* row = s_in + r * 65;
            float s = 0.f;
            #pragma unroll
            for (int u = 1; u <= 16; ++u) s += row[j0 + u];
            s_rs[r * 49 + j0] = s;
            #pragma unroll
            for (int j = 1; j < 12; ++j) {
                s += row[j0 + j + 16] - row[j0 + j];
                s_rs[r * 49 + j0 + j] = s;
            }
        }
        __syncthreads();
        if (t < 192) {
            int j = t >> 2, i0 = (t & 3) * 12;
            int gc = x0 + j - 7;
            bool cin = (unsigned)gc < 512u;
            float s = 0.f;
            #pragma unroll
            for (int u = 1; u <= 16; ++u) s += s_rs[(i0 + u) * 49 + j];
            {
                int gr = y0 + i0 - 7;
                bool in = cin && ((unsigned)gr < 512u);
                s_db[i0 * 49 + j] = in ? (s_in[(i0 + 8) * 65 + j + 8] - s * (1.0f / 256.0f)) : 0.f;
            }
            #pragma unroll
            for (int ii = 1; ii < 12; ++ii) {
                s += s_rs[(i0 + ii + 16) * 49 + j] - s_rs[(i0 + ii) * 49 + j];
                int gr = y0 + i0 + ii - 7;
                bool in = cin && ((unsigned)gr < 512u);
                s_db[(i0 + ii) * 49 + j] = in ? (s_in[(i0 + ii + 8) * 65 + j + 8] - s * (1.0f / 256.0f)) : 0.f;
            }
        }
        __syncthreads();
        float* s_pf = B;             // 48 x 49
        float* s_e  = B + 2352;      // 48 x 33
        float* s_f  = B + 3936;      // 48 x 33
        const float* pfsrc = g_dapf + ((long)b << 18);
        for (int i = t; i < 48 * 48; i += 256) {
            int r = i / 48, c = i - r * 48;
            int gr = y0 + r - 7, gc = x0 + c - 7;
            s_pf[r * 49 + c] = ((unsigned)gr < 512u && (unsigned)gc < 512u) ? pfsrc[gr * WW + gc] : 0.f;
        }
        __syncthreads();
        if (t < 192) {
            int r = t >> 2, w0 = (t & 3) * 8;
            const float* dbr = s_db + r * 49;
            const float* pfr = s_pf + r * 49;
            float se = 0.f, sf = 0.f;
            #pragma unroll
            for (int u = 0; u < 16; ++u) {
                float d = dbr[w0 + u], p = pfr[w0 + u];
                se += d * p; sf += d * d;
            }
            s_e[r * 33 + w0] = se; s_f[r * 33 + w0] = sf;
            #pragma unroll
            for (int w = 1; w < 8; ++w) {
                float d1 = dbr[w0 + w + 15], p1 = pfr[w0 + w + 15];
                float d0 = dbr[w0 + w - 1],  p0 = pfr[w0 + w - 1];
                se += d1 * p1 - d0 * p0;
                sf += d1 * d1 - d0 * d0;
                s_e[r * 33 + w0 + w] = se; s_f[r * 33 + w0 + w] = sf;
            }
        }
        __syncthreads();
        const float* saab = g_saapf + ((long)b << 18);
        for (int i = t; i < 1024; i += 256) {
            int oy = i >> 5, ox = i & 31;
            float sab = 0.f, sbb = 0.f;
            #pragma unroll
            for (int u = 0; u < 16; ++u) {
                sab += s_e[(oy + u) * 33 + ox];
                sbb += s_f[(oy + u) * 33 + ox];
            }
            float saa = saab[(long)(y0 + oy) * WW + x0 + ox];
            s_thr[oy * 32 + ox] = 1.f - sab / (sqrtf(saa * sbb) + EPSF);
        }
    }
    __syncthreads();
    // ===== final part (reuses B[0..9647], keeps s_thr) =====
    {
        float* s_out = B;            // 40 x 41
        float* s_rs2 = B + 1640;     // 40 x 37
        float* s_da  = B + 3120;     // 36 x 37
        float* s_dbp = B + 4452;     // 36 x 37
        float* s_e2  = B + 5784;     // 36 x 33
        float* s_f2  = B + 6972;     // 36 x 33
        const float* src = outp + (long)img * HWs;
        for (int i = t; i < 40 * 40; i += 256) {
            int r = i / 40, c = i - r * 40;
            int gr = y0 + r - 3, gc = x0 + c - 3;
            s_out[r * 41 + c] = ((unsigned)gr < 512u && (unsigned)gc < 512u) ? src[gr * WW + gc] : 0.f;
        }
        const float* dbsrc = g_dbpan + ((long)b << 18);
        for (int i = t; i < 36 * 36; i += 256) {
            int r = i / 36, c = i - r * 36;
            int gr = y0 + r - 1, gc = x0 + c - 1;
            s_dbp[r * 37 + c] = ((unsigned)gr < 512u && (unsigned)gc < 512u) ? dbsrc[gr * WW + gc] : 0.f;
        }
        __syncthreads();
        for (int i = t; i < 40 * 36; i += 256) {
            int r = i / 36, j = i - r * 36;
            float s = 0.f;
            #pragma unroll
            for (int u = 2; u <= 5; ++u) s += s_out[r * 41 + j + u];
            s_rs2[r * 37 + j] = s;
        }
        __syncthreads();
        for (int i = t; i < 36 * 36; i += 256) {
            int ii = i / 36, j = i - ii * 36;
            float s = 0.f;
            #pragma unroll
            for (int u = 1; u <= 4; ++u) s += s_rs2[(ii + u) * 37 + j];
            int gr = y0 + ii - 1, gc = x0 + j - 1;
            bool in = ((unsigned)gr < 512u) && ((unsigned)gc < 512u);
            s_da[ii * 37 + j] = in ? (s_out[(ii + 2) * 41 + j + 2] - s * (1.0f / 16.0f)) : 0.f;
        }
        __syncthreads();
        for (int i = t; i < 36 * 32; i += 256) {
            int r = i >> 5, w = i & 31;
            float se = 0.f, sf = 0.f;
            #pragma unroll
            for (int u = 0; u < 4; ++u) {
                float A = s_da[r * 37 + w + u], Bv = s_dbp[r * 37 + w + u];
                se += A * Bv; sf += A * A;
            }
            s_e2[r * 33 + w] = se; s_f2[r * 33 + w] = sf;
        }
        __syncthreads();
        const float* sbbb = g_sbbpan + ((long)b << 18);
        float acc = 0.f;
        for (int i = t; i < 1024; i += 256) {
            int oy = i >> 5, ox = i & 31;
            float sab = 0.f, saa = 0.f;
            #pragma unroll
            for (int u = 0; u < 4; ++u) {
                sab += s_e2[(oy + u) * 33 + ox];
                saa += s_f2[(oy + u) * 33 + ox];
            }
            float sbb = sbbb[(long)(y0 + oy) * WW + x0 + ox];
            float xc = sab / (sqrtf(saa * sbb) + EPSF);
            xc = fmaxf(xc, -1.f);
            float X = 1.f - xc;
            float thr = s_thr[oy * 32 + ox];
            acc += (X > thr) ? X : 0.f;
        }
        block_reduce1(acc, &g_acc[2]);
    }
}

__global__ void k_out(float* __restrict__ out) {
    if (threadIdx.x == 0) {
        double lspec = g_acc[0] / g_acc[1];
        double lstruct = g_acc[2] / (double)((long)BB * NB * HWs);
        out[0] = (float)(lspec + BETAD * lstruct);
    }
}

// ---------------- launch ----------------
extern "C" void kernel_launch(void* const* d_in, const int* in_sizes, int n_in,
                              void* d_out, int out_size) {
    const float* outputs = (const float*)d_in[0];
    const float* labels  = (const float*)d_in[1];
    const float* inp     = (const float*)d_in[2];
    const float* mtf     = (const float*)d_in[3];
    const float* mask    = (const float*)d_in[4];
    float* out = (float*)d_out;

    k_setup<<<2, 256>>>(mtf);
    k_spec_h<<<BB * NB * 256, 256>>>(outputs);
    k_spec_v<<<dim3(16, BB * NB), 256>>>(labels, mask);
    k_pan_conv<<<dim3(256, BB), 256>>>(inp);
    k_pan_stats<<<dim3(256, BB), 256>>>();
    k_lab_stats<<<dim3(256, BB), 256>>>(labels);
    k_struct<<<dim3(256, BB * NB), 256>>>(inp, outputs);
    k_out<<<1, 32>>>(out);
    (void)in_sizes; (void)n_in; (void)out_size;
}

// round 8
// speedup vs baseline: 1.5905x; 1.0520x over previous
#include <cuda_runtime.h>

#define BB 4
#define NB 8
#define HH 512
#define WW 512
#define HWs (HH*WW)
#define KS 41
#define KR 20
#define SS 128
#define EPSF 1e-20f
#define BETAD 0.25

// ---------------- device scratch ----------------
__device__ float g_v[NB*KS];
__device__ float g_sp[BB*NB*HH*SS];
__device__ float g_panf[BB*HWs];
__device__ float g_dapf[BB*HWs];
__device__ float g_saapf[BB*HWs];
__device__ float g_dbpan[BB*HWs];
__device__ float g_sbbpan[BB*HWs];
__device__ double g_acc[3];

// ---------------- reduction helpers ----------------
__device__ __forceinline__ void block_reduce2(float a, float b, double* d0, double* d1) {
    #pragma unroll
    for (int o = 16; o; o >>= 1) {
        a += __shfl_down_sync(0xffffffffu, a, o);
        b += __shfl_down_sync(0xffffffffu, b, o);
    }
    __shared__ float sa[8], sb[8];
    int lane = threadIdx.x & 31, wid = threadIdx.x >> 5;
    if (lane == 0) { sa[wid] = a; sb[wid] = b; }
    __syncthreads();
    if (wid == 0) {
        int nw = blockDim.x >> 5;
        a = (lane < nw) ? sa[lane] : 0.f;
        b = (lane < nw) ? sb[lane] : 0.f;
        #pragma unroll
        for (int o = 4; o; o >>= 1) {
            a += __shfl_down_sync(0xffffffffu, a, o);
            b += __shfl_down_sync(0xffffffffu, b, o);
        }
        if (lane == 0) { atomicAdd(d0, (double)a); atomicAdd(d1, (double)b); }
    }
}

__device__ __forceinline__ void block_reduce1(float a, double* d0) {
    #pragma unroll
    for (int o = 16; o; o >>= 1) a += __shfl_down_sync(0xffffffffu, a, o);
    __shared__ float sa[8];
    int lane = threadIdx.x & 31, wid = threadIdx.x >> 5;
    if (lane == 0) sa[wid] = a;
    __syncthreads();
    if (wid == 0) {
        int nw = blockDim.x >> 5;
        a = (lane < nw) ? sa[lane] : 0.f;
        #pragma unroll
        for (int o = 4; o; o >>= 1) a += __shfl_down_sync(0xffffffffu, a, o);
        if (lane == 0) atomicAdd(d0, (double)a);
    }
}

// ---------------- setup ----------------
__global__ void k_setup(const float* __restrict__ mtf) {
    int t = blockIdx.x * blockDim.x + threadIdx.x;
    if (t < NB * KS) {
        int k = t / KS, i = t - k * KS;
        g_v[t] = mtf[k * KS * KS + i * KS + KR] / sqrtf(mtf[k * KS * KS + KR * KS + KR]);
    }
    if (t < 3) g_acc[t] = 0.0;
}

// ---------------- L_spec horizontal conv: float4 rolling window ----------------
__global__ void __launch_bounds__(256) k_spec_h(const float* __restrict__ outp) {
    int hp = blockIdx.x & 255;
    int bk = blockIdx.x >> 8;
    int k  = bk & 7;
    __shared__ __align__(16) float s_row[2][556];
    __shared__ float s_v[44];
    int t = threadIdx.x;
    if (t < 44) s_v[t] = (t < KS) ? g_v[k * KS + t] : 0.f;
    if (t < 88) { int r = t / 44, p = t % 44; s_row[r][p < 22 ? p : p - 22 + 534] = 0.f; }
    const float* src = outp + (long)bk * HWs + (long)(2 * hp) * WW;
    for (int i = t; i < 1024; i += 256) {
        int r = i >> 9, c = i & 511;
        s_row[r][22 + c] = src[r * WW + c];
    }
    __syncthreads();
    int r = t >> 7, jj = t & 127;
    const float4* row4 = reinterpret_cast<const float4*>(s_row[r]) + (jj + 1);
    float4 cur = row4[0];
    float s = 0.f;
    #pragma unroll
    for (int tt = 0; tt < 10; ++tt) {
        float4 nxt = row4[tt + 1];
        s += s_v[4*tt] * cur.x + s_v[4*tt+1] * cur.y + s_v[4*tt+2] * cur.z + s_v[4*tt+3] * cur.w;
        cur = nxt;
    }
    s += s_v[40] * cur.x;
    g_sp[((long)bk * HH + 2 * hp + r) * SS + jj] = s;
}

// ---------------- L_spec vertical: smem tile, 4 outputs/thread ----------------
__global__ void __launch_bounds__(256) k_spec_v(const float* __restrict__ labels, const float* __restrict__ mask) {
    int bk = blockIdx.y;
    int kb = bk & 7, b = bk >> 3;
    int ii0 = blockIdx.x * 8;
    __shared__ float s_sp[69][128];
    __shared__ float s_v[KS];
    int t = threadIdx.x;
    if (t < KS) s_v[t] = g_v[kb * KS + t];
    const float* spb = g_sp + (long)bk * HH * SS;
    for (int i = t; i < 69 * 128; i += 256) {
        int m = i >> 7, jj = i & 127;
        int gr = 4 * ii0 - 18 + m;
        s_sp[m][jj] = ((unsigned)gr < 512u) ? spb[(long)gr * SS + jj] : 0.f;
    }
    __syncthreads();
    int jj = t & 127, half = t >> 7;
    int base = 16 * half;
    float o0 = 0.f, o1 = 0.f, o2 = 0.f, o3 = 0.f;
    #pragma unroll
    for (int m = 0; m < 53; ++m) {
        float x = s_sp[base + m][jj];
        if (m <= 40) o0 += s_v[m] * x;
        if (m >= 4 && m <= 44) o1 += s_v[m - 4] * x;
        if (m >= 8 && m <= 48) o2 += s_v[m - 8] * x;
        if (m >= 12) o3 += s_v[m - 12] * x;
    }
    float xs[4] = {o0, o1, o2, o3};
    float num = 0.f, den = 0.f;
    #pragma unroll
    for (int q = 0; q < 4; ++q) {
        int ii = ii0 + 4 * half + q;
        int row = 2 + 4 * ii, col = 2 + 4 * jj;
        float y = labels[((long)(b * (NB + 1) + kb) * HH + row) * WW + col];
        float m2 = mask[((long)kb * HH + row) * WW + col];
        num += fabsf(xs[q] - y) * m2;
        den += m2;
    }
    block_reduce2(num, den, &g_acc[0], &g_acc[1]);
}

// ---------------- fused pan conv: float4 rolling h-phase, 4-out/thread v-phase ----------------
__global__ void __launch_bounds__(256) k_pan_conv(const float* __restrict__ inp) {
    int b = blockIdx.y;
    int x0 = (blockIdx.x & 15) << 5, y0 = (blockIdx.x >> 4) << 5;
    __shared__ __align__(16) float s_in[72 * 76];
    __shared__ float s_mid[72 * 33];
    __shared__ float s_v[44];
    const float* src = inp + ((long)b * (NB + 1) + NB) * HWs;
    int t = threadIdx.x;
    if (t < 44) s_v[t] = (t < KS) ? g_v[t] : 0.f;
    for (int i = t; i < 72 * 72; i += 256) {
        int r = i / 72, c = i - r * 72;
        int gr = y0 + r - 20; gr = gr < 0 ? 0 : (gr > 511 ? 511 : gr);
        int gc = x0 + c - 20; gc = gc < 0 ? 0 : (gc > 511 ? 511 : gc);
        s_in[r * 76 + c] = src[gr * WW + gc];
    }
    __syncthreads();
    for (int i = t; i < 576; i += 256) {
        int r = i >> 3, cg = i & 7;
        const float4* row4 = reinterpret_cast<const float4*>(s_in + r * 76) + cg;
        float o0 = 0.f, o1 = 0.f, o2 = 0.f, o3 = 0.f;
        float4 cur = row4[0];
        #pragma unroll
        for (int tt = 0; tt < 10; ++tt) {
            float4 nxt = row4[tt + 1];
            float v0 = s_v[4*tt], v1 = s_v[4*tt+1], v2 = s_v[4*tt+2], v3 = s_v[4*tt+3];
            o0 += v0 * cur.x + v1 * cur.y + v2 * cur.z + v3 * cur.w;
            o1 += v0 * cur.y + v1 * cur.z + v2 * cur.w + v3 * nxt.x;
            o2 += v0 * cur.z + v1 * cur.w + v2 * nxt.x + v3 * nxt.y;
            o3 += v0 * cur.w + v1 * nxt.x + v2 * nxt.y + v3 * nxt.z;
            cur = nxt;
        }
        float v40 = s_v[40];
        o0 += v40 * cur.x; o1 += v40 * cur.y; o2 += v40 * cur.z; o3 += v40 * cur.w;
        float* dst = s_mid + r * 33 + 4 * cg;
        dst[0] = o0; dst[1] = o1; dst[2] = o2; dst[3] = o3;
    }
    __syncthreads();
    {
        int rg = t >> 5, c = t & 31, r0 = rg * 4;
        float o0 = 0.f, o1 = 0.f, o2 = 0.f, o3 = 0.f;
        #pragma unroll
        for (int m = 0; m < 44; ++m) {
            float x = s_mid[(r0 + m) * 33 + c];
            if (m <= 40) o0 += s_v[m] * x;
            if (m >= 1 && m <= 41) o1 += s_v[m - 1] * x;
            if (m >= 2 && m <= 42) o2 += s_v[m - 2] * x;
            if (m >= 3) o3 += s_v[m - 3] * x;
        }
        float* dst = g_panf + ((long)b << 18) + (long)(y0 + r0) * WW + x0 + c;
        dst[0] = o0; dst[WW] = o1; dst[2 * WW] = o2; dst[3 * WW] = o3;
    }
}

// ---------------- fused pan stats: dapf (w=8) + saapf, all sliding ----------------
__global__ void __launch_bounds__(256) k_pan_stats() {
    int b = blockIdx.y;
    int x0 = (blockIdx.x & 15) << 5, y0 = (blockIdx.x >> 4) << 5;
    __shared__ float s_pf[64][65];
    __shared__ float s_rs[64][49];
    __shared__ float s_da[48][49];
    __shared__ float s_q[48][33];
    const float* src = g_panf + ((long)b << 18);
    int t = threadIdx.x;
    for (int i = t; i < 64 * 64; i += 256) {
        int r = i >> 6, c = i & 63;
        int gr = y0 + r - 15, gc = x0 + c - 15;
        s_pf[r][c] = ((unsigned)gr < 512u && (unsigned)gc < 512u) ? src[gr * WW + gc] : 0.f;
    }
    __syncthreads();
    // rowsum16 sliding: 64 rows x 4 segs of 12
    {
        int r = t >> 2, j0 = (t & 3) * 12;
        float s = 0.f;
        #pragma unroll
        for (int u = 1; u <= 16; ++u) s += s_pf[r][j0 + u];
        s_rs[r][j0] = s;
        #pragma unroll
        for (int j = 1; j < 12; ++j) {
            s += s_pf[r][j0 + j + 16] - s_pf[r][j0 + j];
            s_rs[r][j0 + j] = s;
        }
    }
    __syncthreads();
    // da colsum16 sliding: 48 cols x 4 segs of 12
    if (t < 192) {
        int j = t >> 2, i0 = (t & 3) * 12;
        int gc = x0 + j - 7;
        bool cin = (unsigned)gc < 512u;
        float s = 0.f;
        #pragma unroll
        for (int u = 1; u <= 16; ++u) s += s_rs[i0 + u][j];
        {
            int gr = y0 + i0 - 7;
            bool in = cin && ((unsigned)gr < 512u);
            float d = in ? (s_pf[i0 + 8][j + 8] - s * (1.0f / 256.0f)) : 0.f;
            s_da[i0][j] = d;
            if (i0 >= 7 && i0 < 39 && j >= 7 && j < 39)
                g_dapf[((long)b << 18) + (long)gr * WW + gc] = d;
        }
        #pragma unroll
        for (int ii = 1; ii < 12; ++ii) {
            s += s_rs[i0 + ii + 16][j] - s_rs[i0 + ii][j];
            int gr = y0 + i0 + ii - 7;
            bool in = cin && ((unsigned)gr < 512u);
            float d = in ? (s_pf[i0 + ii + 8][j + 8] - s * (1.0f / 256.0f)) : 0.f;
            s_da[i0 + ii][j] = d;
            if (i0 + ii >= 7 && i0 + ii < 39 && j >= 7 && j < 39)
                g_dapf[((long)b << 18) + (long)gr * WW + gc] = d;
        }
    }
    __syncthreads();
    // sq rowsum16 sliding: 48 rows x 4 segs of 8
    if (t < 192) {
        int r = t >> 2, w0 = (t & 3) * 8;
        float s = 0.f;
        #pragma unroll
        for (int u = 0; u < 16; ++u) { float x = s_da[r][w0 + u]; s += x * x; }
        s_q[r][w0] = s;
        #pragma unroll
        for (int w = 1; w < 8; ++w) {
            float x1 = s_da[r][w0 + w + 15], x0v = s_da[r][w0 + w - 1];
            s += x1 * x1 - x0v * x0v;
            s_q[r][w0 + w] = s;
        }
    }
    __syncthreads();
    // saa colsum16 sliding: 32 cols x 8 segs of 4
    {
        int ox = t & 31, r0 = (t >> 5) * 4;
        float s = 0.f;
        #pragma unroll
        for (int u = 0; u < 16; ++u) s += s_q[r0 + u][ox];
        float* dst = g_saapf + ((long)b << 18) + (long)(y0 + r0) * WW + x0 + ox;
        dst[0] = s;
        #pragma unroll
        for (int q = 1; q < 4; ++q) {
            s += s_q[r0 + q + 15][ox] - s_q[r0 + q - 1][ox];
            dst[q * WW] = s;
        }
    }
}

// ---------------- fused label-pan stats: dbpan (w=2) + sbbpan ----------------
__global__ void __launch_bounds__(256) k_lab_stats(const float* __restrict__ labels) {
    int b = blockIdx.y;
    int x0 = (blockIdx.x & 15) << 5, y0 = (blockIdx.x >> 4) << 5;
    __shared__ float s_lb[40][41];
    __shared__ float s_rs[40][37];
    __shared__ float s_db[36][37];
    __shared__ float s_q[36][33];
    const float* src = labels + ((long)b * (NB + 1) + NB) * HWs;
    int t = threadIdx.x;
    for (int i = t; i < 40 * 40; i += 256) {
        int r = i / 40, c = i - r * 40;
        int gr = y0 + r - 3, gc = x0 + c - 3;
        s_lb[r][c] = ((unsigned)gr < 512u && (unsigned)gc < 512u) ? src[gr * WW + gc] : 0.f;
    }
    __syncthreads();
    for (int i = t; i < 40 * 36; i += 256) {
        int r = i / 36, j = i - r * 36;
        float s = 0.f;
        #pragma unroll
        for (int u = 2; u <= 5; ++u) s += s_lb[r][j + u];
        s_rs[r][j] = s;
    }
    __syncthreads();
    for (int i = t; i < 36 * 36; i += 256) {
        int ii = i / 36, j = i - ii * 36;
        float s = 0.f;
        #pragma unroll
        for (int u = 1; u <= 4; ++u) s += s_rs[ii + u][j];
        int gr = y0 + ii - 1, gc = x0 + j - 1;
        bool in = ((unsigned)gr < 512u) && ((unsigned)gc < 512u);
        float d = in ? (s_lb[ii + 2][j + 2] - s * (1.0f / 16.0f)) : 0.f;
        s_db[ii][j] = d;
        if (ii >= 1 && ii < 33 && j >= 1 && j < 33)
            g_dbpan[((long)b << 18) + (long)gr * WW + gc] = d;
    }
    __syncthreads();
    for (int i = t; i < 36 * 32; i += 256) {
        int r = i >> 5, w = i & 31;
        float s = 0.f;
        #pragma unroll
        for (int u = 0; u < 4; ++u) { float x = s_db[r][w + u]; s += x * x; }
        s_q[r][w] = s;
    }
    __syncthreads();
    for (int i = t; i < 1024; i += 256) {
        int oy = i >> 5, ox = i & 31;
        float s = 0.f;
        #pragma unroll
        for (int u = 0; u < 4; ++u) s += s_q[oy + u][ox];
        g_sbbpan[((long)b << 18) + (long)(y0 + oy) * WW + x0 + ox] = s;
    }
}

// ---------------- fused structural: thr + final in one kernel ----------------
__global__ void __launch_bounds__(256) k_struct(const float* __restrict__ inp, const float* __restrict__ outp) {
    int img = blockIdx.y;
    int b = img >> 3, kb = img & 7;
    int x0 = (blockIdx.x & 15) << 5, y0 = (blockIdx.x >> 4) << 5;
    __shared__ float B[10672];
    float* s_thr = B + 9648;         // 32 x 32 (persists)
    int t = threadIdx.x;
    // ===== thr part =====
    {
        float* s_in = B;             // 64 x 65
        float* s_rs = B + 4160;      // 64 x 49
        float* s_db = B + 7296;      // 48 x 49
        const float* src = inp + ((long)b * (NB + 1) + kb) * HWs;
        for (int i = t; i < 64 * 64; i += 256) {
            int r = i >> 6, c = i & 63;
            int gr = y0 + r - 15, gc = x0 + c - 15;
            s_in[r * 65 + c] = ((unsigned)gr < 512u && (unsigned)gc < 512u) ? src[gr * WW + gc] : 0.f;
        }
        __syncthreads();
        {
            int r = t >> 2, j0 = (t & 3) * 12;
            const float* row = s_in + r * 65;
            float s = 0.f;
            #pragma unroll
            for (int u = 1; u <= 16; ++u) s += row[j0 + u];
            s_rs[r * 49 + j0] = s;
            #pragma unroll
            for (int j = 1; j < 12; ++j) {
                s += row[j0 + j + 16] - row[j0 + j];
                s_rs[r * 49 + j0 + j] = s;
            }
        }
        __syncthreads();
        if (t < 192) {
            int j = t >> 2, i0 = (t & 3) * 12;
            int gc = x0 + j - 7;
            bool cin = (unsigned)gc < 512u;
            float s = 0.f;
            #pragma unroll
            for (int u = 1; u <= 16; ++u) s += s_rs[(i0 + u) * 49 + j];
            {
                int gr = y0 + i0 - 7;
                bool in = cin && ((unsigned)gr < 512u);
                s_db[i0 * 49 + j] = in ? (s_in[(i0 + 8) * 65 + j + 8] - s * (1.0f / 256.0f)) : 0.f;
            }
            #pragma unroll
            for (int ii = 1; ii < 12; ++ii) {
                s += s_rs[(i0 + ii + 16) * 49 + j] - s_rs[(i0 + ii) * 49 + j];
                int gr = y0 + i0 + ii - 7;
                bool in = cin && ((unsigned)gr < 512u);
                s_db[(i0 + ii) * 49 + j] = in ? (s_in[(i0 + ii + 8) * 65 + j + 8] - s * (1.0f / 256.0f)) : 0.f;
            }
        }
        __syncthreads();
        float* s_pf = B;             // 48 x 49
        float* s_e  = B + 2352;      // 48 x 33
        float* s_f  = B + 3936;      // 48 x 33
        const float* pfsrc = g_dapf + ((long)b << 18);
        for (int i = t; i < 48 * 48; i += 256) {
            int r = i / 48, c = i - r * 48;
            int gr = y0 + r - 7, gc = x0 + c - 7;
            s_pf[r * 49 + c] = ((unsigned)gr < 512u && (unsigned)gc < 512u) ? pfsrc[gr * WW + gc] : 0.f;
        }
        __syncthreads();
        if (t < 192) {
            int r = t >> 2, w0 = (t & 3) * 8;
            const float* dbr = s_db + r * 49;
            const float* pfr = s_pf + r * 49;
            float se = 0.f, sf = 0.f;
            #pragma unroll
            for (int u = 0; u < 16; ++u) {
                float d = dbr[w0 + u], p = pfr[w0 + u];
                se += d * p; sf += d * d;
            }
            s_e[r * 33 + w0] = se; s_f[r * 33 + w0] = sf;
            #pragma unroll
            for (int w = 1; w < 8; ++w) {
                float d1 = dbr[w0 + w + 15], p1 = pfr[w0 + w + 15];
                float d0 = dbr[w0 + w - 1],  p0 = pfr[w0 + w - 1];
                se += d1 * p1 - d0 * p0;
                sf += d1 * d1 - d0 * d0;
                s_e[r * 33 + w0 + w] = se; s_f[r * 33 + w0 + w] = sf;
            }
        }
        __syncthreads();
        // colsum16 sliding -> thr: 32 cols x 8 segs of 4
        {
            int ox = t & 31, r0 = (t >> 5) * 4;
            const float* saab = g_saapf + ((long)b << 18);
            float sab = 0.f, sbb = 0.f;
            #pragma unroll
            for (int u = 0; u < 16; ++u) {
                sab += s_e[(r0 + u) * 33 + ox];
                sbb += s_f[(r0 + u) * 33 + ox];
            }
            {
                float saa = saab[(long)(y0 + r0) * WW + x0 + ox];
                s_thr[r0 * 32 + ox] = 1.f - sab / (sqrtf(saa * sbb) + EPSF);
            }
            #pragma unroll
            for (int q = 1; q < 4; ++q) {
                sab += s_e[(r0 + q + 15) * 33 + ox] - s_e[(r0 + q - 1) * 33 + ox];
                sbb += s_f[(r0 + q + 15) * 33 + ox] - s_f[(r0 + q - 1) * 33 + ox];
                float saa = saab[(long)(y0 + r0 + q) * WW + x0 + ox];
                s_thr[(r0 + q) * 32 + ox] = 1.f - sab / (sqrtf(saa * sbb) + EPSF);
            }
        }
    }
    __syncthreads();
    // ===== final part =====
    {
        float* s_out = B;            // 40 x 41
        float* s_rs2 = B + 1640;     // 40 x 37
        float* s_da  = B + 3120;     // 36 x 37
        float* s_dbp = B + 4452;     // 36 x 37
        float* s_e2  = B + 5784;     // 36 x 33
        float* s_f2  = B + 6972;     // 36 x 33
        const float* src = outp + (long)img * HWs;
        for (int i = t; i < 40 * 40; i += 256) {
            int r = i / 40, c = i - r * 40;
            int gr = y0 + r - 3, gc = x0 + c - 3;
            s_out[r * 41 + c] = ((unsigned)gr < 512u && (unsigned)gc < 512u) ? src[gr * WW + gc] : 0.f;
        }
        const float* dbsrc = g_dbpan + ((long)b << 18);
        for (int i = t; i < 36 * 36; i += 256) {
            int r = i / 36, c = i - r * 36;
            int gr = y0 + r - 1, gc = x0 + c - 1;
            s_dbp[r * 37 + c] = ((unsigned)gr < 512u && (unsigned)gc < 512u) ? dbsrc[gr * WW + gc] : 0.f;
        }
        __syncthreads();
        for (int i = t; i < 40 * 36; i += 256) {
            int r = i / 36, j = i - r * 36;
            float s = 0.f;
            #pragma unroll
            for (int u = 2; u <= 5; ++u) s += s_out[r * 41 + j + u];
            s_rs2[r * 37 + j] = s;
        }
        __syncthreads();
        for (int i = t; i < 36 * 36; i += 256) {
            int ii = i / 36, j = i - ii * 36;
            float s = 0.f;
            #pragma unroll
            for (int u = 1; u <= 4; ++u) s += s_rs2[(ii + u) * 37 + j];
            int gr = y0 + ii - 1, gc = x0 + j - 1;
            bool in = ((unsigned)gr < 512u) && ((unsigned)gc < 512u);
            s_da[ii * 37 + j] = in ? (s_out[(ii + 2) * 41 + j + 2] - s * (1.0f / 16.0f)) : 0.f;
        }
        __syncthreads();
        for (int i = t; i < 36 * 32; i += 256) {
            int r = i >> 5, w = i & 31;
            float se = 0.f, sf = 0.f;
            #pragma unroll
            for (int u = 0; u < 4; ++u) {
                float A = s_da[r * 37 + w + u], Bv = s_dbp[r * 37 + w + u];
                se += A * Bv; sf += A * A;
            }
            s_e2[r * 33 + w] = se; s_f2[r * 33 + w] = sf;
        }
        __syncthreads();
        // colsum4 sliding + masked accumulation: 32 cols x 8 segs of 4
        const float* sbbb = g_sbbpan + ((long)b << 18);
        float acc = 0.f;
        {
            int ox = t & 31, r0 = (t >> 5) * 4;
            float sab = 0.f, saa = 0.f;
            #pragma unroll
            for (int u = 0; u < 4; ++u) {
                sab += s_e2[(r0 + u) * 33 + ox];
                saa += s_f2[(r0 + u) * 33 + ox];
            }
            #pragma unroll
            for (int q = 0; q < 4; ++q) {
                if (q > 0) {
                    sab += s_e2[(r0 + q + 3) * 33 + ox] - s_e2[(r0 + q - 1) * 33 + ox];
                    saa += s_f2[(r0 + q + 3) * 33 + ox] - s_f2[(r0 + q - 1) * 33 + ox];
                }
                float sbb = sbbb[(long)(y0 + r0 + q) * WW + x0 + ox];
                float xc = sab / (sqrtf(saa * sbb) + EPSF);
                xc = fmaxf(xc, -1.f);
                float X = 1.f - xc;
                float thr = s_thr[(r0 + q) * 32 + ox];
                acc += (X > thr) ? X : 0.f;
            }
        }
        block_reduce1(acc, &g_acc[2]);
    }
}

__global__ void k_out(float* __restrict__ out) {
    if (threadIdx.x == 0) {
        double lspec = g_acc[0] / g_acc[1];
        double lstruct = g_acc[2] / (double)((long)BB * NB * HWs);
        out[0] = (float)(lspec + BETAD * lstruct);
    }
}

// ---------------- launch ----------------
extern "C" void kernel_launch(void* const* d_in, const int* in_sizes, int n_in,
                              void* d_out, int out_size) {
    const float* outputs = (const float*)d_in[0];
    const float* labels  = (const float*)d_in[1];
    const float* inp     = (const float*)d_in[2];
    const float* mtf     = (const float*)d_in[3];
    const float* mask    = (const float*)d_in[4];
    float* out = (float*)d_out;

    k_setup<<<2, 256>>>(mtf);
    k_spec_h<<<BB * NB * 256, 256>>>(outputs);
    k_spec_v<<<dim3(16, BB * NB), 256>>>(labels, mask);
    k_pan_conv<<<dim3(256, BB), 256>>>(inp);
    k_pan_stats<<<dim3(256, BB), 256>>>();
    k_lab_stats<<<dim3(256, BB), 256>>>(labels);
    k_struct<<<dim3(256, BB * NB), 256>>>(inp, outputs);
    k_out<<<1, 32>>>(out);
    (void)in_sizes; (void)n_in; (void)out_size;
}